// round 4
// baseline (speedup 1.0000x reference)
#include <cuda_runtime.h>

// ---------------------------------------------------------------------------
// TiDHy reference collapses analytically:
//   r is zeroed every step, r2 stays zero  =>  hypernet/temporal path is dead.
//   x_hat = x_bar = b_sd;  temp_loss = r2_losses = 0;  r0, r2 outputs = 0.
//   sl_rhat = (1/B) * sum_{b,t=0..T-1,d} (b_sd[d]-X[b,t,d])^2
//   sl_rbar = (1/B) * sum_{b,t=1..T-1,d} (b_sd[d]-X[b,t,d])^2
// Output layout (flattened tuple, fp32):
//   [0]=sl_rhat [1]=sl_rbar [2]=temp_loss [3]=r2_losses
//   [4 .. 4+B*R)      = r0  (zeros)
//   [.. out_size)     = r2  (zeros)
// ---------------------------------------------------------------------------

static constexpr int Bn = 128;
static constexpr int T  = 32;
static constexpr int D  = 512;
static constexpr int N4 = Bn * T * D / 4;   // float4 count = 524288

__device__ double        g_sum[2];   // [0] = S_all, [1] = S_t0   (zero-init, reset by finalize)
__device__ unsigned int  g_done;     // block-completion ticket (wraps via atomicInc)

__global__ __launch_bounds__(256)
void tidhy_reduce_kernel(const float4* __restrict__ X4,
                         const float4* __restrict__ bsd4,
                         float* __restrict__ out, int out_size)
{
    const int tid    = blockIdx.x * blockDim.x + threadIdx.x;
    const int stride = gridDim.x * blockDim.x;

    // ---- zero-fill output tail (r0, r2, and scalars 2..3 are written by finalize) ----
    for (int i = 4 + tid; i < out_size; i += stride)
        out[i] = 0.0f;

    // ---- grid-stride squared-error reduction ----
    constexpr int D4 = D / 4;          // 128 float4 per (b,t) row
    double s_all = 0.0, s_t0 = 0.0;

    for (int i = tid; i < N4; i += stride) {
        float4 x = X4[i];
        int d4 = i % D4;
        int t  = (i / D4) % T;
        float4 b = bsd4[d4];           // 2 KB vector: L1/L2 resident broadcast
        float dx0 = b.x - x.x, dx1 = b.y - x.y;
        float dx2 = b.z - x.z, dx3 = b.w - x.w;
        double v = (double)dx0 * dx0 + (double)dx1 * dx1
                 + (double)dx2 * dx2 + (double)dx3 * dx3;
        s_all += v;
        if (t == 0) s_t0 += v;
    }

    // ---- intra-block reduction (warp shuffles + smem) ----
    for (int o = 16; o > 0; o >>= 1) {
        s_all += __shfl_down_sync(0xffffffffu, s_all, o);
        s_t0  += __shfl_down_sync(0xffffffffu, s_t0,  o);
    }
    __shared__ double sh_all[8], sh_t0[8];
    int lane = threadIdx.x & 31;
    int wrp  = threadIdx.x >> 5;
    if (lane == 0) { sh_all[wrp] = s_all; sh_t0[wrp] = s_t0; }
    __syncthreads();

    if (wrp == 0) {
        int nwarps = blockDim.x >> 5;
        s_all = (lane < nwarps) ? sh_all[lane] : 0.0;
        s_t0  = (lane < nwarps) ? sh_t0[lane]  : 0.0;
        for (int o = 4; o > 0; o >>= 1) {
            s_all += __shfl_down_sync(0xffffffffu, s_all, o);
            s_t0  += __shfl_down_sync(0xffffffffu, s_t0,  o);
        }
        if (lane == 0) {
            atomicAdd(&g_sum[0], s_all);
            atomicAdd(&g_sum[1], s_t0);
            __threadfence();
            // ticket: atomicInc wraps to 0 when old == gridDim.x-1, so the
            // counter self-resets for the next graph replay.
            unsigned int ticket = atomicInc(&g_done, gridDim.x - 1);
            if (ticket == gridDim.x - 1) {
                double S_all = g_sum[0];
                double S_t0  = g_sum[1];
                out[0] = (float)(S_all / (double)Bn);            // sl_rhat
                out[1] = (float)((S_all - S_t0) / (double)Bn);   // sl_rbar
                out[2] = 0.0f;                                   // temp_loss
                out[3] = 0.0f;                                   // r2_losses
                g_sum[0] = 0.0;                                  // reset for next replay
                g_sum[1] = 0.0;
            }
        }
    }
}

extern "C" void kernel_launch(void* const* d_in, const int* in_sizes, int n_in,
                              void* d_out, int out_size)
{
    // metadata order: X, rng, W_sd, b_sd, W_h1, b_h1, ln_scale, ln_bias,
    //                 W_h2, b_h2, W_h3, b_h3, temporal
    const float4* X4   = (const float4*)d_in[0];
    const float4* bsd4 = (const float4*)d_in[3];
    float* out = (float*)d_out;

    // 1024 blocks x 256 threads: 2 grid-stride iterations over 524288 float4,
    // full-chip coverage, one kernel, graph-capturable, allocation-free.
    tidhy_reduce_kernel<<<1024, 256>>>(X4, bsd4, out, out_size);
}

// round 5
// speedup vs baseline: 3.1045x; 3.1045x over previous
#include <cuda_runtime.h>

// ---------------------------------------------------------------------------
// TiDHy reference collapses analytically (validated in R3, rel_err 1.2e-7):
//   r zeroed each step, r2 stays zero  =>  hypernet/temporal path dead.
//   sl_rhat = (1/B) * sum_{b,t=0..T-1,d} (b_sd[d]-X[b,t,d])^2
//   sl_rbar = (1/B) * sum_{b,t=1..T-1,d} (b_sd[d]-X[b,t,d])^2
//   temp_loss = r2_losses = 0; r0, r2 outputs = zeros.
//
// R4 optimization: remove FP64 from the hot path (serial DFMA chains + double
// shuffles were the latency bottleneck), one float4 per thread (max MLP,
// no loop), and replace threadfence+atomics+ticket with a 2nd tiny graph
// kernel reducing per-block fp32 partials in double.
// ---------------------------------------------------------------------------

static constexpr int Bn = 128;
static constexpr int T  = 32;
static constexpr int D  = 512;
static constexpr int N4 = Bn * T * D / 4;       // 524288 float4
static constexpr int BLK = 1024;
static constexpr int GRID = N4 / BLK;           // 512 blocks, 1 float4/thread

__device__ float g_partial_all[GRID];
__device__ float g_partial_t0[GRID];

__global__ __launch_bounds__(BLK)
void tidhy_partial_kernel(const float4* __restrict__ X4,
                          const float4* __restrict__ bsd4,
                          float* __restrict__ out, int out_size)
{
    const int tid = blockIdx.x * BLK + threadIdx.x;

    // zero-fill output tail (scalars [0..3] written by finalize kernel)
    for (int i = 4 + tid; i < out_size; i += GRID * BLK)
        out[i] = 0.0f;

    // one float4 per thread — fully coalesced, no loop, no serial chain
    constexpr int D4 = D / 4;                    // 128 float4 per (b,t) row
    float4 x = X4[tid];
    float4 b = bsd4[tid & (D4 - 1)];             // 2KB vector, L1-broadcast
    int   t  = (tid >> 7) & (T - 1);

    float dx0 = b.x - x.x, dx1 = b.y - x.y;
    float dx2 = b.z - x.z, dx3 = b.w - x.w;
    float v = dx0 * dx0 + dx1 * dx1 + dx2 * dx2 + dx3 * dx3;
    float v0 = (t == 0) ? v : 0.0f;

    // warp tree reduce (fp32: 5 levels, two sums pipelined)
    #pragma unroll
    for (int o = 16; o > 0; o >>= 1) {
        v  += __shfl_down_sync(0xffffffffu, v,  o);
        v0 += __shfl_down_sync(0xffffffffu, v0, o);
    }

    __shared__ float sh_all[32], sh_t0[32];
    int lane = threadIdx.x & 31;
    int wrp  = threadIdx.x >> 5;
    if (lane == 0) { sh_all[wrp] = v; sh_t0[wrp] = v0; }
    __syncthreads();

    if (wrp == 0) {
        v  = sh_all[lane];
        v0 = sh_t0[lane];
        #pragma unroll
        for (int o = 16; o > 0; o >>= 1) {
            v  += __shfl_down_sync(0xffffffffu, v,  o);
            v0 += __shfl_down_sync(0xffffffffu, v0, o);
        }
        if (lane == 0) {
            g_partial_all[blockIdx.x] = v;
            g_partial_t0[blockIdx.x]  = v0;
        }
    }
}

// Single-block finalize: reduce 512 partials per sum in double, write scalars.
__global__ __launch_bounds__(512)
void tidhy_finalize_kernel(float* __restrict__ out)
{
    int tid = threadIdx.x;                       // 512 threads = GRID
    double s  = (double)g_partial_all[tid];
    double s0 = (double)g_partial_t0[tid];

    #pragma unroll
    for (int o = 16; o > 0; o >>= 1) {
        s  += __shfl_down_sync(0xffffffffu, s,  o);
        s0 += __shfl_down_sync(0xffffffffu, s0, o);
    }
    __shared__ double sh[16], sh0[16];
    int lane = tid & 31, wrp = tid >> 5;
    if (lane == 0) { sh[wrp] = s; sh0[wrp] = s0; }
    __syncthreads();

    if (wrp == 0 && lane < 16) {
        s  = sh[lane];
        s0 = sh0[lane];
        #pragma unroll
        for (int o = 8; o > 0; o >>= 1) {
            s  += __shfl_down_sync(0x0000ffffu, s,  o);
            s0 += __shfl_down_sync(0x0000ffffu, s0, o);
        }
        if (lane == 0) {
            out[0] = (float)(s / (double)Bn);          // sl_rhat (t=0..T-1)
            out[1] = (float)((s - s0) / (double)Bn);   // sl_rbar (t=1..T-1)
            out[2] = 0.0f;                             // temp_loss
            out[3] = 0.0f;                             // r2_losses
        }
    }
}

extern "C" void kernel_launch(void* const* d_in, const int* in_sizes, int n_in,
                              void* d_out, int out_size)
{
    // metadata order: X, rng, W_sd, b_sd, W_h1, b_h1, ln_scale, ln_bias,
    //                 W_h2, b_h2, W_h3, b_h3, temporal
    const float4* X4   = (const float4*)d_in[0];
    const float4* bsd4 = (const float4*)d_in[3];
    float* out = (float*)d_out;

    tidhy_partial_kernel<<<GRID, BLK>>>(X4, bsd4, out, out_size);
    tidhy_finalize_kernel<<<1, 512>>>(out);
}